// round 4
// baseline (speedup 1.0000x reference)
#include <cuda_runtime.h>
#include <math.h>

#define NN 200000
#define NE 3200000
#define NEG_SLOPE 0.02f

#define FFMA2(d, a, b, c) \
    asm("fma.rn.f32x2 %0, %1, %2, %3;" : "=l"(d) : "l"(a), "l"(b), "l"(c))
#define PACK2(d, lo, hi) \
    asm("mov.b64 %0, {%1, %2};" : "=l"(d) : "f"(lo), "f"(hi))
#define UNPACK2(lo, hi, s) \
    asm("mov.b64 {%0, %1}, %2;" : "=f"(lo), "=f"(hi) : "l"(s))

typedef unsigned long long u64t;

// ---------------- scratch (device globals; no allocation allowed) -----------
__device__ int   d_cnt[NN];
__device__ int   d_rowptr[NN + 1];
__device__ int   d_cursor[NN];
__device__ int   d_cols[NE];
__device__ float d_dinv[NN];
__device__ __align__(16) float d_gbuf[NN * 16];
__device__ __align__(16) float d_hbuf[NN * 16];
__device__ int   d_bsum[256];

// ---------------- graph prep -------------------------------------------------
__global__ void k_zero_cnt() {
    int i = blockIdx.x * blockDim.x + threadIdx.x;
    if (i < NN) d_cnt[i] = 0;
}

__global__ void k_count(const int* __restrict__ dst) {
    int e = blockIdx.x * blockDim.x + threadIdx.x;
    if (e < NE) atomicAdd(&d_cnt[dst[e]], 1);
}

// block-wise inclusive scan (1024 elems/block) -> exclusive prefix in rowptr
__global__ void k_scan1() {
    __shared__ int sh[1024];
    int i = blockIdx.x * 1024 + threadIdx.x;
    int v = (i < NN) ? d_cnt[i] : 0;
    sh[threadIdx.x] = v;
    __syncthreads();
    for (int off = 1; off < 1024; off <<= 1) {
        int t = (threadIdx.x >= off) ? sh[threadIdx.x - off] : 0;
        __syncthreads();
        sh[threadIdx.x] += t;
        __syncthreads();
    }
    if (i < NN) d_rowptr[i] = sh[threadIdx.x] - v;  // exclusive
    if (threadIdx.x == 1023) d_bsum[blockIdx.x] = sh[1023];
}

__global__ void k_scan2(int nb) {
    if (blockIdx.x == 0 && threadIdx.x == 0) {
        int run = 0;
        for (int b = 0; b < nb; b++) { int t = d_bsum[b]; d_bsum[b] = run; run += t; }
        d_rowptr[NN] = run;  // == NE
    }
}

// finalize rowptr, init cursor, and compute dinv = rsqrt(deg+1) (fused)
__global__ void k_scan3() {
    int i = blockIdx.x * blockDim.x + threadIdx.x;
    if (i < NN) {
        int r = d_rowptr[i] + d_bsum[i >> 10];
        d_rowptr[i] = r;
        d_cursor[i] = r;
        d_dinv[i]   = rsqrtf((float)(d_cnt[i] + 1));
    }
}

__global__ void k_fill(const int* __restrict__ src, const int* __restrict__ dst) {
    int e = blockIdx.x * blockDim.x + threadIdx.x;
    if (e < NE) {
        int p = atomicAdd(&d_cursor[dst[e]], 1);
        d_cols[p] = src[e];
    }
}

// ---------------- layer 1 GEMM: g = dinv ⊙ (x @ W1), x is [NN,128] ----------
// 128 threads/block, 32 nodes/block; packed f32x2 FFMA (2 FFMA2/k vs 4 FFMA).
__global__ void __launch_bounds__(128) k_gemm1(const float* __restrict__ x,
                                               const float* __restrict__ W1) {
    __shared__ __align__(16) float xs[32 * 132];
    __shared__ __align__(16) float ws[2048];  // W1 [128][16] linear copy
    int t  = threadIdx.x;
    int n0 = blockIdx.x * 32;

#pragma unroll
    for (int r = 0; r < 16; r++) ws[t + 128 * r] = W1[t + 128 * r];

    const float4* x4 = (const float4*)x;
#pragma unroll
    for (int r = 0; r < 8; r++) {
        int idx = t + 128 * r;           // 0..1023 float4s
        int nd  = idx >> 5;              // node in tile
        int kq  = idx & 31;              // float4 within row
        int node = n0 + nd;
        float4 v = make_float4(0.f, 0.f, 0.f, 0.f);
        if (node < NN) v = x4[(size_t)node * 32 + kq];
        *(float4*)&xs[nd * 132 + kq * 4] = v;
    }
    __syncthreads();

    int nd = t >> 2;      // 0..31 node in tile
    int fq = t & 3;       // feature quad 0..3
    const float* xr = &xs[nd * 132];
    u64t acc01 = 0, acc23 = 0;
#pragma unroll 8
    for (int k = 0; k < 128; k++) {
        float xv = xr[k];
        u64t xv2; PACK2(xv2, xv, xv);
        ulonglong2 w2 = *(const ulonglong2*)&ws[k * 16 + fq * 4];
        FFMA2(acc01, xv2, w2.x, acc01);
        FFMA2(acc23, xv2, w2.y, acc23);
    }
    int node = n0 + nd;
    if (node < NN) {
        float s = d_dinv[node];
        float a0, a1, a2, a3;
        UNPACK2(a0, a1, acc01);
        UNPACK2(a2, a3, acc23);
        ((float4*)d_gbuf)[node * 4 + fq] =
            make_float4(a0 * s, a1 * s, a2 * s, a3 * s);
    }
}

// ---------------- fused aggregation (+ optional next-layer 16x16 GEMM) ------
// Warp per node. Lanes 0-15 (half 0) process even edges, lanes 16-31 (half 1)
// odd edges -> 8 gathers in flight per warp (x4 unroll each half). Halves
// combine via shfl_xor(16). Optionally fuses the next layer's 16x16 GEMM:
// gout_i = dinv_i * (h_i @ Wn) via half-warp shuffles.
// NN = 25000*8, so every warp owns a valid node (no predicates, safe shfl).
__global__ void __launch_bounds__(256) k_agg_f(int flip,
                                               const float* __restrict__ b,
                                               const float* __restrict__ Wn,
                                               int relu) {
    const float* __restrict__ gin = flip ? d_hbuf : d_gbuf;
    float* __restrict__ gout      = flip ? d_gbuf : d_hbuf;
    __shared__ float Wsh[256];
    int tid = threadIdx.x;
    if (Wn) {                      // uniform branch across block
        Wsh[tid] = Wn[tid];        // 16x16
        __syncthreads();
    }
    int lane = tid & 31;
    int warp = tid >> 5;
    int node = blockIdx.x * 8 + warp;
    int f    = lane & 15;
    int half = lane >> 4;

    // self-loop term counted once (half 0 only)
    float acc = half ? 0.f : gin[node * 16 + f];
    int beg = d_rowptr[node];
    int end = d_rowptr[node + 1];
    int e = beg + half;            // this half's first edge (stride 2)
    for (; e + 6 < end; e += 8) {
        int s0 = d_cols[e],     s1 = d_cols[e + 2];
        int s2 = d_cols[e + 4], s3 = d_cols[e + 6];
        float v0 = gin[s0 * 16 + f];
        float v1 = gin[s1 * 16 + f];
        float v2 = gin[s2 * 16 + f];
        float v3 = gin[s3 * 16 + f];
        acc += v0; acc += v1; acc += v2; acc += v3;
    }
    for (; e < end; e += 2) acc += gin[d_cols[e] * 16 + f];

    // combine halves: all 32 lanes end with the full sum for feature f
    acc += __shfl_xor_sync(0xffffffffu, acc, 16);

    float dn = d_dinv[node];
    float o  = dn * acc + b[f];
    if (relu) o = fmaxf(o, 0.f);

    if (!Wn) {
        if (half == 0) gout[node * 16 + f] = o;
        return;
    }

    // next-layer GEMM in-register: g2[f] = dn * sum_k o_k * Wn[k][f]
    // (both halves hold identical o per f; shfl within own half)
    int base = lane & 16;
    float a2 = 0.f;
#pragma unroll
    for (int k = 0; k < 16; k++) {
        float v = __shfl_sync(0xffffffffu, o, base | k);
        a2 += v * Wsh[k * 16 + f];
    }
    if (half == 0) gout[node * 16 + f] = dn * a2;
}

// ---------------- fused MLP (16->64->16->2) + log_softmax -------------------
__global__ void __launch_bounds__(256) k_mlp(const float* __restrict__ M1,
                                             const float* __restrict__ mb1,
                                             const float* __restrict__ M2,
                                             const float* __restrict__ mb2,
                                             const float* __restrict__ M3,
                                             const float* __restrict__ mb3,
                                             float* __restrict__ out) {
    __shared__ __align__(16) float4 m1[256];   // [16][64]
    __shared__ __align__(16) float4 m2[256];   // [64][16]
    __shared__ __align__(16) float  sm3[32];   // [16][2]
    __shared__ __align__(16) float  sb1[64];
    __shared__ __align__(16) float  sb2[16];
    __shared__ __align__(16) float  sb3[2];
    int tid = threadIdx.x;
    m1[tid] = ((const float4*)M1)[tid];
    m2[tid] = ((const float4*)M2)[tid];
    if (tid < 32) sm3[tid] = M3[tid];
    if (tid < 64) sb1[tid] = mb1[tid];
    if (tid < 16) sb2[tid] = mb2[tid];
    if (tid < 2)  sb3[tid] = mb3[tid];
    __syncthreads();

    int i = blockIdx.x * 256 + tid;
    if (i >= NN) return;

    const float4* hin = (const float4*)&d_hbuf[i * 16];
    float4 h0 = hin[0], h1 = hin[1], h2 = hin[2], h3 = hin[3];
    float hk[16] = { h0.x, h0.y, h0.z, h0.w, h1.x, h1.y, h1.z, h1.w,
                     h2.x, h2.y, h2.z, h2.w, h3.x, h3.y, h3.z, h3.w };

    // ---- layer 1: 16 -> 64, packed f32x2 ----
    u64t acc[32];
    const u64t* bias1 = (const u64t*)sb1;
#pragma unroll
    for (int j = 0; j < 32; j++) acc[j] = bias1[j];
    const ulonglong2* mm1 = (const ulonglong2*)m1;
#pragma unroll
    for (int k = 0; k < 16; k++) {
        float v = hk[k];
        u64t v2; PACK2(v2, v, v);
#pragma unroll
        for (int j4 = 0; j4 < 16; j4++) {
            ulonglong2 w = mm1[k * 16 + j4];
            FFMA2(acc[j4 * 2 + 0], v2, w.x, acc[j4 * 2 + 0]);
            FFMA2(acc[j4 * 2 + 1], v2, w.y, acc[j4 * 2 + 1]);
        }
    }
    float a[64];
#pragma unroll
    for (int j = 0; j < 32; j++) {
        float lo, hi;
        UNPACK2(lo, hi, acc[j]);
        a[j * 2 + 0] = lo > 0.f ? lo : NEG_SLOPE * lo;
        a[j * 2 + 1] = hi > 0.f ? hi : NEG_SLOPE * hi;
    }

    // ---- layer 2: 64 -> 16, packed f32x2 ----
    u64t zacc[8];
    const u64t* bias2 = (const u64t*)sb2;
#pragma unroll
    for (int j = 0; j < 8; j++) zacc[j] = bias2[j];
    const ulonglong2* mm2 = (const ulonglong2*)m2;
#pragma unroll
    for (int k = 0; k < 64; k++) {
        float v = a[k];
        u64t v2; PACK2(v2, v, v);
#pragma unroll
        for (int j4 = 0; j4 < 4; j4++) {
            ulonglong2 w = mm2[k * 4 + j4];
            FFMA2(zacc[j4 * 2 + 0], v2, w.x, zacc[j4 * 2 + 0]);
            FFMA2(zacc[j4 * 2 + 1], v2, w.y, zacc[j4 * 2 + 1]);
        }
    }
    float z[16];
#pragma unroll
    for (int j = 0; j < 8; j++) {
        float lo, hi;
        UNPACK2(lo, hi, zacc[j]);
        z[j * 2 + 0] = lo > 0.f ? lo : NEG_SLOPE * lo;
        z[j * 2 + 1] = hi > 0.f ? hi : NEG_SLOPE * hi;
    }

    // ---- layer 3: 16 -> 2, + log_softmax ----
    float l0 = sb3[0], l1 = sb3[1];
#pragma unroll
    for (int k = 0; k < 16; k++) {
        l0 += z[k] * sm3[k * 2 + 0];
        l1 += z[k] * sm3[k * 2 + 1];
    }
    float m   = fmaxf(l0, l1);
    float lse = m + __logf(__expf(l0 - m) + __expf(l1 - m));
    out[i * 2 + 0] = l0 - lse;
    out[i * 2 + 1] = l1 - lse;
}

// ---------------- launch -----------------------------------------------------
extern "C" void kernel_launch(void* const* d_in, const int* in_sizes, int n_in,
                              void* d_out, int out_size) {
    const float* x    = (const float*)d_in[0];
    const int*   data = (const int*)d_in[1];   // [2, NE]: src row then dst row
    const float* W1   = (const float*)d_in[2];
    const float* b1   = (const float*)d_in[3];
    const float* W2   = (const float*)d_in[4];
    const float* b2   = (const float*)d_in[5];
    const float* W3   = (const float*)d_in[6];
    const float* b3   = (const float*)d_in[7];
    const float* M1   = (const float*)d_in[8];
    const float* mb1  = (const float*)d_in[9];
    const float* M2   = (const float*)d_in[10];
    const float* mb2  = (const float*)d_in[11];
    const float* M3   = (const float*)d_in[12];
    const float* mb3  = (const float*)d_in[13];
    float* out = (float*)d_out;

    const int* src = data;
    const int* dst = data + NE;

    const int NB_N  = (NN + 255) / 256;    // 782
    const int NB_E  = (NE + 255) / 256;    // 12500
    const int NB_SC = (NN + 1023) / 1024;  // 196
    const int NB_AG = NN / 8;              // 25000 (exact)

    // graph prep
    k_zero_cnt<<<NB_N, 256>>>();
    k_count<<<NB_E, 256>>>(dst);
    k_scan1<<<NB_SC, 1024>>>();
    k_scan2<<<1, 32>>>(NB_SC);
    k_scan3<<<NB_N, 256>>>();
    k_fill<<<NB_E, 256>>>(src, dst);

    // layer 1: gemm into gbuf
    k_gemm1<<<(NN + 31) / 32, 128>>>(x, W1);
    // layer 1 agg + fused layer-2 GEMM:  gbuf -> hbuf
    k_agg_f<<<NB_AG, 256>>>(0, b1, W2, 1);
    // layer 2 agg + fused layer-3 GEMM:  hbuf -> gbuf
    k_agg_f<<<NB_AG, 256>>>(1, b2, W3, 1);
    // layer 3 agg (no act, no fused gemm): gbuf -> hbuf
    k_agg_f<<<NB_AG, 256>>>(0, b3, nullptr, 0);

    // MLP + log_softmax
    k_mlp<<<NB_N, 256>>>(M1, mb1, M2, mb2, M3, mb3, out);
}